// round 1
// baseline (speedup 1.0000x reference)
#include <cuda_runtime.h>
#include <math.h>

#define NN 50000
#define NE 150000
#define NG 2000
#define DD 75
#define TW 5
#define FO 15
#define NL 4
#define AVGLOG 1.1308269950720914f

// ---------------- scratch (device globals; no allocs) ----------------
__device__ float g_H[NN * DD];          // node features
__device__ float g_CAB[NN * 750];       // [A(dst part) | B(src part)] per node
__device__ float g_AGG[NN * 1500];      // [T,4,D] aggregates per node
__device__ float g_G[NN * 225];         // [T,45] post partial
__device__ float g_HWX[NN * DD];
__device__ float g_Z[NN * DD];
__device__ float g_Y[NN * DD];
__device__ float g_amp[NN];
__device__ float g_invamp[NN];
__device__ int   g_deg[NN];
__device__ int   g_rowptr[NN + 1];
__device__ int   g_cursor[NN];
__device__ int   g_csr[NE];             // src | (attr<<20)
__device__ int   g_bsum[256];
__device__ int   g_boffs[256];
__device__ float g_Wcat[NL * 75 * 750];
__device__ float g_Etab[NL * 4 * 375];
__device__ float g_WG[NL * TW * 300 * 45];
__device__ float g_Wxcat[NL * 75 * 75];
__device__ double g_bnS[DD];
__device__ double g_bnQ[DD];
__device__ float g_pool[NG * DD];
__device__ float g_z1[NG * 50];
__device__ float g_z2[NG * 25];

// ---------------- generic tiled SGEMM (optionally batched over z) ----------------
// C[z] = A[z] @ B[z] + bias, act=1 -> relu
__global__ void sgemm_kernel(const float* __restrict__ A, int lda, long strideA,
                             const float* __restrict__ B, int ldb, long strideB,
                             float* __restrict__ C, int ldc, long strideC,
                             int M, int N, int K,
                             const float* __restrict__ bias, int act) {
    const int BM = 64, BN = 64, BK = 16, TM = 4, TN = 4;
    __shared__ float As[BK][BM + 1];
    __shared__ float Bs[BK][BN];
    const float* Ab = A + (long)blockIdx.z * strideA;
    const float* Bb = B + (long)blockIdx.z * strideB;
    float* Cb = C + (long)blockIdx.z * strideC;
    int m0 = blockIdx.y * BM, n0 = blockIdx.x * BN;
    int tid = threadIdx.x;
    int tx = tid % 16, ty = tid / 16;
    float acc[TM][TN];
#pragma unroll
    for (int i = 0; i < TM; i++)
#pragma unroll
        for (int j = 0; j < TN; j++) acc[i][j] = 0.f;

    for (int k0 = 0; k0 < K; k0 += BK) {
        for (int i = tid; i < BM * BK; i += 256) {
            int r = i / BK, c = i % BK;
            int gm = m0 + r, gk = k0 + c;
            As[c][r] = (gm < M && gk < K) ? Ab[(long)gm * lda + gk] : 0.f;
        }
        for (int i = tid; i < BK * BN; i += 256) {
            int r = i / BN, c = i % BN;
            int gk = k0 + r, gn = n0 + c;
            Bs[r][c] = (gk < K && gn < N) ? Bb[(long)gk * ldb + gn] : 0.f;
        }
        __syncthreads();
#pragma unroll
        for (int kk = 0; kk < BK; kk++) {
            float a[TM], b[TN];
#pragma unroll
            for (int i = 0; i < TM; i++) a[i] = As[kk][ty * TM + i];
#pragma unroll
            for (int j = 0; j < TN; j++) b[j] = Bs[kk][tx * TN + j];
#pragma unroll
            for (int i = 0; i < TM; i++)
#pragma unroll
                for (int j = 0; j < TN; j++) acc[i][j] += a[i] * b[j];
        }
        __syncthreads();
    }
#pragma unroll
    for (int i = 0; i < TM; i++) {
        int gm = m0 + ty * TM + i;
        if (gm >= M) continue;
#pragma unroll
        for (int j = 0; j < TN; j++) {
            int gn = n0 + tx * TN + j;
            if (gn >= N) continue;
            float v = acc[i][j] + (bias ? bias[gn] : 0.f);
            if (act) v = fmaxf(v, 0.f);
            Cb[(long)gm * ldc + gn] = v;
        }
    }
}

// ---------------- small utility kernels ----------------
__global__ void zero_i(int* p, int n) {
    int i = blockIdx.x * blockDim.x + threadIdx.x;
    if (i < n) p[i] = 0;
}
__global__ void zero_f(float* p, int n) {
    int i = blockIdx.x * blockDim.x + threadIdx.x;
    if (i < n) p[i] = 0.f;
}
__global__ void zero_d75(double* a, double* b) {
    int i = threadIdx.x;
    if (i < DD) { a[i] = 0.0; b[i] = 0.0; }
}

__global__ void hist_k(const int* __restrict__ ei, int* __restrict__ deg) {
    int e = blockIdx.x * blockDim.x + threadIdx.x;
    if (e < NE) atomicAdd(&deg[ei[NE + e]], 1);
}

__global__ void scan_chunks(const int* __restrict__ in, int* __restrict__ out,
                            int* __restrict__ bsum, int n) {
    __shared__ int s[512];
    int b = blockIdx.x, t = threadIdx.x;
    int idx = b * 512 + t;
    int v = (idx < n) ? in[idx] : 0;
    s[t] = v;
    __syncthreads();
    for (int off = 1; off < 512; off <<= 1) {
        int x = (t >= off) ? s[t - off] : 0;
        __syncthreads();
        s[t] += x;
        __syncthreads();
    }
    if (idx < n) out[idx] = s[t] - v;  // exclusive within chunk
    if (t == 511) bsum[b] = s[511];
}
__global__ void scan_sums(const int* __restrict__ sums, int* __restrict__ offs, int nb) {
    __shared__ int s[128];
    int t = threadIdx.x;
    int v = (t < nb) ? sums[t] : 0;
    s[t] = v;
    __syncthreads();
    for (int off = 1; off < 128; off <<= 1) {
        int x = (t >= off) ? s[t - off] : 0;
        __syncthreads();
        s[t] += x;
        __syncthreads();
    }
    if (t < nb) offs[t] = s[t] - v;
}
__global__ void scan_add(int* __restrict__ rowptr, const int* __restrict__ offs) {
    int i = blockIdx.x * blockDim.x + threadIdx.x;
    if (i < NN) rowptr[i] += offs[i >> 9];
    if (i == 0) rowptr[NN] = NE;
}

__global__ void fill_csr(const int* __restrict__ ei, const int* __restrict__ ea,
                         const int* __restrict__ rowptr, int* __restrict__ cursor,
                         int* __restrict__ csr) {
    int e = blockIdx.x * blockDim.x + threadIdx.x;
    if (e >= NE) return;
    int d = ei[NE + e];
    int pos = rowptr[d] + atomicAdd(&cursor[d], 1);
    csr[pos] = ei[e] | (ea[e] << 20);
}

__global__ void amp_k(const int* __restrict__ rowptr, float* __restrict__ amp,
                      float* __restrict__ invamp) {
    int i = blockIdx.x * blockDim.x + threadIdx.x;
    if (i >= NN) return;
    int dg = rowptr[i + 1] - rowptr[i];
    float a = logf((float)max(dg, 1) + 1.f) / AVGLOG;
    amp[i] = a;
    invamp[i] = 1.f / a;
}

__global__ void embed_k(const int* __restrict__ x, const float* __restrict__ emb,
                        float* __restrict__ H) {
    int i = blockIdx.x * blockDim.x + threadIdx.x;
    if (i >= NN * DD) return;
    H[i] = emb[x[i / DD] * DD + i % DD];
}

// ---------------- weight prep ----------------
__global__ void prep_wcat(const float* __restrict__ Wpre, float* __restrict__ Wcat) {
    int i = blockIdx.x * blockDim.x + threadIdx.x;
    if (i >= NL * 75 * 750) return;
    int l = i / (75 * 750), r = i % (75 * 750);
    int k = r / 750, j = r % 750;
    int part = j / 375, j2 = j % 375;
    int t = j2 / 75, f = j2 % 75;
    int c = part * 75 + k;
    Wcat[i] = Wpre[((l * TW + t) * 225 + c) * 75 + f];
}

__global__ void prep_etab(const float* __restrict__ edge_emb, const float* __restrict__ We,
                          const float* __restrict__ be, const float* __restrict__ Wpre,
                          const float* __restrict__ bpre, float* __restrict__ Etab) {
    int a = blockIdx.x, l = blockIdx.y;
    __shared__ float ev[75];
    int t0 = threadIdx.x;
    if (t0 < 75) {
        float s = be[l * 75 + t0];
        for (int c = 0; c < 50; c++) s += edge_emb[a * 50 + c] * We[(l * 50 + c) * 75 + t0];
        ev[t0] = s;
    }
    __syncthreads();
    for (int j = t0; j < 375; j += blockDim.x) {
        int t = j / 75, f = j % 75;
        float s = bpre[(l * TW + t) * 75 + f];
        for (int d = 0; d < 75; d++)
            s += ev[d] * Wpre[((l * TW + t) * 225 + 150 + d) * 75 + f];
        Etab[(l * 4 + a) * 375 + j] = s;
    }
}

__global__ void prep_wg(const float* __restrict__ Wpost, float* __restrict__ WG) {
    int i = blockIdx.x * blockDim.x + threadIdx.x;
    if (i >= NL * TW * 300 * 45) return;
    int lt = i / (300 * 45), r = i % (300 * 45);
    int c = r / 45, col = r % 45;
    int g = col / 15, f = col % 15;
    WG[i] = Wpost[(lt * 975 + 75 + g * 300 + c) * 15 + f];
}

__global__ void prep_wxcat(const float* __restrict__ Wpost, float* __restrict__ Wx) {
    int i = blockIdx.x * blockDim.x + threadIdx.x;
    if (i >= NL * 75 * 75) return;
    int l = i / (75 * 75), r = i % (75 * 75);
    int c = r / 75, j = r % 75;
    int t = j / 15, f = j % 15;
    Wx[i] = Wpost[((l * TW + t) * 975 + c) * 15 + f];
}

// ---------------- PNA aggregation (mean/min/max/std over CSR) ----------------
__global__ void pna_agg(const float* __restrict__ CAB, const float* __restrict__ Etab,
                        const int* __restrict__ rowptr, const int* __restrict__ csr,
                        float* __restrict__ AGG) {
    int n = blockIdx.x;
    int j = threadIdx.x;
    if (j >= 375) return;
    float adst = CAB[n * 750 + j];
    int beg = rowptr[n], end = rowptr[n + 1];
    float s = 0.f, sq = 0.f, mn = 3.4e38f, mx = -3.4e38f;
    for (int e = beg; e < end; e++) {
        int p = csr[e];
        int src = p & 0xFFFFF;
        int attr = p >> 20;
        float v = adst + CAB[src * 750 + 375 + j] + Etab[attr * 375 + j];
        s += v;
        sq += v * v;
        mn = fminf(mn, v);
        mx = fmaxf(mx, v);
    }
    int dg = end - beg;
    float denom = fmaxf((float)dg, 1.f);
    float mean = s / denom, msq = sq / denom;
    float sd = sqrtf(fmaxf(msq - mean * mean, 0.f) + 1e-5f);
    if (dg == 0) { mn = 0.f; mx = 0.f; }
    int t = j / 75, f = j % 75;
    float* o = AGG + n * 1500 + t * 300;
    o[f] = mean;
    o[75 + f] = mn;
    o[150 + f] = mx;
    o[225 + f] = sd;
}

// ---------------- combine towers + scalers ----------------
__global__ void combine_k(const float* __restrict__ HWX, const float* __restrict__ G,
                          const float* __restrict__ amp, const float* __restrict__ invamp,
                          const float* __restrict__ bpost, float* __restrict__ Z) {
    int i = blockIdx.x * blockDim.x + threadIdx.x;
    if (i >= NN * DD) return;
    int n = i / DD, j = i % DD;
    int t = j / 15, f = j % 15;
    const float* g = G + n * 225 + t * 45;
    Z[i] = HWX[i] + g[f] + amp[n] * g[15 + f] + invamp[n] * g[30 + f] + bpost[t * 15 + f];
}

// ---------------- batchnorm ----------------
__global__ void bn_stats(const float* __restrict__ Y, double* __restrict__ S,
                         double* __restrict__ Q) {
    __shared__ float ss[4][75], sq[4][75];
    int f = threadIdx.x, w = threadIdx.y;
    int base = blockIdx.x * 64;
    float s = 0.f, q = 0.f;
    for (int r = w; r < 64; r += 4) {
        int n = base + r;
        if (n < NN) {
            float v = Y[n * DD + f];
            s += v;
            q += v * v;
        }
    }
    ss[w][f] = s;
    sq[w][f] = q;
    __syncthreads();
    if (w == 0) {
        float st = ss[0][f] + ss[1][f] + ss[2][f] + ss[3][f];
        float qt = sq[0][f] + sq[1][f] + sq[2][f] + sq[3][f];
        atomicAdd(&S[f], (double)st);
        atomicAdd(&Q[f], (double)qt);
    }
}

__global__ void bn_apply(const float* __restrict__ Y, const double* __restrict__ S,
                         const double* __restrict__ Q, const float* __restrict__ gamma,
                         const float* __restrict__ beta, float* __restrict__ H) {
    int i = blockIdx.x * blockDim.x + threadIdx.x;
    if (i >= NN * DD) return;
    int f = i % DD;
    double mu = S[f] / (double)NN;
    double var = Q[f] / (double)NN - mu * mu;
    float inv = rsqrtf((float)var + 1e-5f);
    float v = gamma[f] * ((Y[i] - (float)mu) * inv) + beta[f];
    H[i] = fmaxf(v, 0.f);
}

// ---------------- pooling ----------------
__global__ void pool_k(const int* __restrict__ batch, const float* __restrict__ H,
                       float* __restrict__ pool) {
    int i = blockIdx.x * blockDim.x + threadIdx.x;
    if (i >= NN * DD) return;
    int n = i / DD, f = i % DD;
    atomicAdd(&pool[batch[n] * DD + f], H[i]);
}

// ---------------- launch ----------------
static inline void sgemm(const float* A, int lda, long sA, const float* B, int ldb, long sB,
                         float* C, int ldc, long sC, int M, int N, int K, const float* bias,
                         int act, int nz) {
    dim3 grid((N + 63) / 64, (M + 63) / 64, nz);
    sgemm_kernel<<<grid, 256>>>(A, lda, sA, B, ldb, sB, C, ldc, sC, M, N, K, bias, act);
}

extern "C" void kernel_launch(void* const* d_in, const int* in_sizes, int n_in,
                              void* d_out, int out_size) {
    const int* x = (const int*)d_in[0];
    const int* ei = (const int*)d_in[1];
    const int* ea = (const int*)d_in[2];
    const int* batch = (const int*)d_in[3];
    const float* node_emb = (const float*)d_in[4];
    const float* edge_emb = (const float*)d_in[5];
    const float* We = (const float*)d_in[6];
    const float* be = (const float*)d_in[7];
    const float* Wpre = (const float*)d_in[8];
    const float* bpre = (const float*)d_in[9];
    const float* Wpost = (const float*)d_in[10];
    const float* bpost = (const float*)d_in[11];
    const float* Wlin = (const float*)d_in[12];
    const float* blin = (const float*)d_in[13];
    const float* gamma = (const float*)d_in[14];
    const float* beta = (const float*)d_in[15];
    const float* W1 = (const float*)d_in[16];
    const float* b1 = (const float*)d_in[17];
    const float* W2 = (const float*)d_in[18];
    const float* b2 = (const float*)d_in[19];
    const float* W3 = (const float*)d_in[20];
    const float* b3 = (const float*)d_in[21];
    float* out = (float*)d_out;

    float *H, *CAB, *AGG, *G, *HWX, *Z, *Y, *amp, *invamp, *Wcat, *Etab, *WG, *Wx, *pool, *z1, *z2;
    int *deg, *rowptr, *cursor, *csr, *bsum, *boffs;
    double *bnS, *bnQ;
    cudaGetSymbolAddress((void**)&H, g_H);
    cudaGetSymbolAddress((void**)&CAB, g_CAB);
    cudaGetSymbolAddress((void**)&AGG, g_AGG);
    cudaGetSymbolAddress((void**)&G, g_G);
    cudaGetSymbolAddress((void**)&HWX, g_HWX);
    cudaGetSymbolAddress((void**)&Z, g_Z);
    cudaGetSymbolAddress((void**)&Y, g_Y);
    cudaGetSymbolAddress((void**)&amp, g_amp);
    cudaGetSymbolAddress((void**)&invamp, g_invamp);
    cudaGetSymbolAddress((void**)&deg, g_deg);
    cudaGetSymbolAddress((void**)&rowptr, g_rowptr);
    cudaGetSymbolAddress((void**)&cursor, g_cursor);
    cudaGetSymbolAddress((void**)&csr, g_csr);
    cudaGetSymbolAddress((void**)&bsum, g_bsum);
    cudaGetSymbolAddress((void**)&boffs, g_boffs);
    cudaGetSymbolAddress((void**)&Wcat, g_Wcat);
    cudaGetSymbolAddress((void**)&Etab, g_Etab);
    cudaGetSymbolAddress((void**)&WG, g_WG);
    cudaGetSymbolAddress((void**)&Wx, g_Wxcat);
    cudaGetSymbolAddress((void**)&bnS, g_bnS);
    cudaGetSymbolAddress((void**)&bnQ, g_bnQ);
    cudaGetSymbolAddress((void**)&pool, g_pool);
    cudaGetSymbolAddress((void**)&z1, g_z1);
    cudaGetSymbolAddress((void**)&z2, g_z2);

    // ---- graph structure prep ----
    zero_i<<<(NN + 255) / 256, 256>>>(deg, NN);
    zero_i<<<(NN + 255) / 256, 256>>>(cursor, NN);
    hist_k<<<(NE + 255) / 256, 256>>>(ei, deg);
    int nchunks = (NN + 511) / 512;  // 98
    scan_chunks<<<nchunks, 512>>>(deg, rowptr, bsum, NN);
    scan_sums<<<1, 128>>>(bsum, boffs, nchunks);
    scan_add<<<(NN + 255) / 256, 256>>>(rowptr, boffs);
    fill_csr<<<(NE + 255) / 256, 256>>>(ei, ea, rowptr, cursor, csr);
    amp_k<<<(NN + 255) / 256, 256>>>(rowptr, amp, invamp);
    embed_k<<<(NN * DD + 255) / 256, 256>>>(x, node_emb, H);

    // ---- weight prep (all layers) ----
    prep_wcat<<<(NL * 75 * 750 + 255) / 256, 256>>>(Wpre, Wcat);
    prep_etab<<<dim3(4, NL), 384>>>(edge_emb, We, be, Wpre, bpre, Etab);
    prep_wg<<<(NL * TW * 300 * 45 + 255) / 256, 256>>>(Wpost, WG);
    prep_wxcat<<<(NL * 75 * 75 + 255) / 256, 256>>>(Wpost, Wx);

    // ---- layers ----
    for (int l = 0; l < NL; l++) {
        // CAB = H @ Wcat_l  [NN,75] x [75,750]
        sgemm(H, 75, 0, Wcat + l * 75 * 750, 750, 0, CAB, 750, 0, NN, 750, 75, nullptr, 0, 1);
        // multi-aggregator
        pna_agg<<<NN, 384>>>(CAB, Etab + l * 4 * 375, rowptr, csr, AGG);
        // G[t] = AGG[:, t*300:(t+1)*300] @ WG[l][t]  (batched over towers)
        sgemm(AGG, 1500, 300, WG + l * TW * 300 * 45, 45, 300 * 45, G, 225, 45, NN, 45, 300,
              nullptr, 0, TW);
        // HWX = H @ Wxcat_l
        sgemm(H, 75, 0, Wx + l * 75 * 75, 75, 0, HWX, 75, 0, NN, 75, 75, nullptr, 0, 1);
        // combine scalers + bpost
        combine_k<<<(NN * DD + 255) / 256, 256>>>(HWX, G, amp, invamp, bpost + l * TW * FO, Z);
        // Y = Z @ Wlin_l + blin_l
        sgemm(Z, 75, 0, Wlin + l * 75 * 75, 75, 0, Y, 75, 0, NN, 75, 75, blin + l * 75, 0, 1);
        // batchnorm + relu -> H
        zero_d75<<<1, 128>>>(bnS, bnQ);
        bn_stats<<<(NN + 63) / 64, dim3(75, 4)>>>(Y, bnS, bnQ);
        bn_apply<<<(NN * DD + 255) / 256, 256>>>(Y, bnS, bnQ, gamma + l * DD, beta + l * DD, H);
    }

    // ---- pooling + MLP ----
    zero_f<<<(NG * DD + 255) / 256, 256>>>(pool, NG * DD);
    pool_k<<<(NN * DD + 255) / 256, 256>>>(batch, H, pool);
    sgemm(pool, 75, 0, W1, 50, 0, z1, 50, 0, NG, 50, 75, b1, 1, 1);
    sgemm(z1, 50, 0, W2, 25, 0, z2, 25, 0, NG, 25, 50, b2, 1, 1);
    sgemm(z2, 25, 0, W3, 1, 0, out, 1, 0, NG, 1, 25, b3, 0, 1);
}